// round 13
// baseline (speedup 1.0000x reference)
#include <cuda_runtime.h>
#include <cuda_fp16.h>
#include <cstdint>

#define DIMK   256
#define NOUT   512
#define MROWS  32768
#define NEMB   255
#define NEDGE  4194304

typedef unsigned int u32;

// device scratch
__device__ float4 g_xpad[MROWS];
__device__ u32    g_Wfrag[NOUT * DIMK / 2];            // W  fp16, frag order (256KB)
__device__ u32    g_Afrag[(size_t)MROWS * DIMK / 2];   // h  fp16, frag order (16MB)

// smem: 4 stages x (A 8KB + B 4KB) = 48KB
#define STAGE_BYTES 12288
#define SM_SIZE     (4 * STAGE_BYTES)

__device__ __forceinline__ u32 pack_h2(float lo, float hi) {
    __half2 h = __floats2half2_rn(lo, hi);
    return *(u32*)&h;
}
__device__ __forceinline__ u32 smem_u32(const void* p) {
    u32 a;
    asm("{ .reg .u64 t; cvta.to.shared.u64 t, %1; cvt.u32.u64 %0, t; }" : "=r"(a) : "l"(p));
    return a;
}
__device__ __forceinline__ void cp16(u32 dst, const void* src) {
    asm volatile("cp.async.cg.shared.global [%0], [%1], 16;" :: "r"(dst), "l"(src));
}
#define CP_COMMIT() asm volatile("cp.async.commit_group;" ::: "memory")
#define CP_WAIT2()  asm volatile("cp.async.wait_group 2;" ::: "memory")

__device__ __forceinline__ void mma_f16(float* c, uint4 a, uint2 b) {
    asm volatile(
        "mma.sync.aligned.m16n8k16.row.col.f32.f16.f16.f32 "
        "{%0,%1,%2,%3}, {%4,%5,%6,%7}, {%8,%9}, {%0,%1,%2,%3};"
        : "+f"(c[0]), "+f"(c[1]), "+f"(c[2]), "+f"(c[3])
        : "r"(a.x), "r"(a.y), "r"(a.z), "r"(a.w), "r"(b.x), "r"(b.y));
}

// ---------------------------------------------------------------------------
// kernel0: xpad (blocks 0..127) + Wfrag (blocks 128..255)
// ---------------------------------------------------------------------------
__global__ __launch_bounds__(256) void k0_setup(
    const float* __restrict__ x, const float* __restrict__ W)
{
    int bid = blockIdx.x, tid = threadIdx.x;
    if (bid < 128) {
        int i = bid * 256 + tid;
        g_xpad[i] = make_float4(x[3 * i], x[3 * i + 1], x[3 * i + 2], 0.f);
    } else {
        int b = bid - 128;
        #pragma unroll
        for (int i = 0; i < 2; i++) {
            int p      = b * 512 + i * 256 + tid;      // uint2 index
            int lane   = p & 31;
            int ks     = (p >> 5) & 1;
            int tile_n = (p >> 6) & 15;
            int kc     = (p >> 10) & 7;
            int nb     = p >> 13;
            int n  = nb * 128 + tile_n * 8 + (lane >> 2);
            int k0 = kc * 32 + ks * 16 + (lane & 3) * 2;
            uint2 v;
            v.x = pack_h2(W[k0 * NOUT + n],       W[(k0 + 1) * NOUT + n]);
            v.y = pack_h2(W[(k0 + 8) * NOUT + n], W[(k0 + 9) * NOUT + n]);
            ((uint2*)g_Wfrag)[p] = v;
        }
    }
}

// ---------------------------------------------------------------------------
// kernel1, grid 2048: even bidx -> edges (1024 blocks x 4096 edges, sync-free,
// 16 edges/thread, 4 unrolled rounds for MLP), odd bidx -> Afrag build.
// ---------------------------------------------------------------------------
__global__ __launch_bounds__(256) void k1_edges_afrag(
    const int*   __restrict__ edges,   // [2,E]
    const float* __restrict__ charges,
    const int*   __restrict__ cats,
    const float* __restrict__ nmask,
    const float* __restrict__ emb,     // [100,255]
    float*       __restrict__ radial,  // [E]
    float*       __restrict__ cd)      // [E,3]
{
    const int tid  = threadIdx.x;
    const int bidx = blockIdx.x;

    if ((bidx & 1) == 0) {
        // ===================== edges: 4096 per block =====================
        const int eid = bidx >> 1;                // 0..1023
        const int4* rowp = (const int4*)edges;
        const int4* colp = (const int4*)(edges + NEDGE);

        #pragma unroll
        for (int it = 0; it < 4; it++) {
            int q4 = eid * 1024 + it * 256 + tid;  // int4/float4 index (4 edges)
            int4 r = __ldg(&rowp[q4]);
            int4 c = __ldg(&colp[q4]);
            float4 p0 = __ldg(&g_xpad[r.x]);
            float4 p1 = __ldg(&g_xpad[r.y]);
            float4 p2 = __ldg(&g_xpad[r.z]);
            float4 p3 = __ldg(&g_xpad[r.w]);
            float4 q0 = __ldg(&g_xpad[c.x]);
            float4 q1 = __ldg(&g_xpad[c.y]);
            float4 q2 = __ldg(&g_xpad[c.z]);
            float4 q3 = __ldg(&g_xpad[c.w]);

            float d0x = p0.x - q0.x, d0y = p0.y - q0.y, d0z = p0.z - q0.z;
            float d1x = p1.x - q1.x, d1y = p1.y - q1.y, d1z = p1.z - q1.z;
            float d2x = p2.x - q2.x, d2y = p2.y - q2.y, d2z = p2.z - q2.z;
            float d3x = p3.x - q3.x, d3y = p3.y - q3.y, d3z = p3.z - q3.z;

            float4 rad;
            rad.x = d0x*d0x + d0y*d0y + d0z*d0z;
            rad.y = d1x*d1x + d1y*d1y + d1z*d1z;
            rad.z = d2x*d2x + d2y*d2y + d2z*d2z;
            rad.w = d3x*d3x + d3y*d3y + d3z*d3z;

            float i0 = 1.0f / (sqrtf(rad.x + 1e-8f) + 1.0f);
            float i1 = 1.0f / (sqrtf(rad.y + 1e-8f) + 1.0f);
            float i2 = 1.0f / (sqrtf(rad.z + 1e-8f) + 1.0f);
            float i3 = 1.0f / (sqrtf(rad.w + 1e-8f) + 1.0f);

            ((float4*)radial)[q4] = rad;

            float4* dst = (float4*)cd + (size_t)q4 * 3;
            dst[0] = make_float4(d0x * i0, d0y * i0, d0z * i0, d1x * i1);
            dst[1] = make_float4(d1y * i1, d1z * i1, d2x * i2, d2y * i2);
            dst[2] = make_float4(d2z * i2, d3x * i3, d3y * i3, d3z * i3);
        }
    } else {
        // ===================== Afrag build =====================
        const int b = bidx >> 1;                  // 0..1023
        #pragma unroll
        for (int i = 0; i < 4; i++) {
            int q      = b * 1024 + i * 256 + tid;   // uint4 index
            int lane   = q & 31;
            int ks     = (q >> 5) & 1;
            int tile_m = (q >> 6) & 7;
            int kc     = (q >> 9) & 7;
            int mb     = q >> 12;
            int m  = mb * 128 + tile_m * 16 + (lane >> 2);
            int k0 = kc * 32 + ks * 16 + (lane & 3) * 2;

            float msk0 = __ldg(&nmask[m]);
            float msk1 = __ldg(&nmask[m + 8]);
            int   cat0 = __ldg(&cats[m]);
            int   cat1 = __ldg(&cats[m + 8]);
            auto hval = [&](int mm, float msk, int cat, int k) -> float {
                return (k == 0) ? __ldg(&charges[mm]) * msk
                                : __ldg(&emb[cat * NEMB + k - 1]) * msk;
            };
            uint4 v;
            v.x = pack_h2(hval(m,     msk0, cat0, k0),     hval(m,     msk0, cat0, k0 + 1));
            v.y = pack_h2(hval(m + 8, msk1, cat1, k0),     hval(m + 8, msk1, cat1, k0 + 1));
            v.z = pack_h2(hval(m,     msk0, cat0, k0 + 8), hval(m,     msk0, cat0, k0 + 9));
            v.w = pack_h2(hval(m + 8, msk1, cat1, k0 + 8), hval(m + 8, msk1, cat1, k0 + 9));
            ((uint4*)g_Afrag)[q] = v;
        }
    }
}

// ---------------------------------------------------------------------------
// kernel2: pure GEMM. 2048 blocks, 128x64 tiles, 8 warps (4M x 2N, 32x32),
// K = 8 chunks of 32, 4-stage cp.async pipeline, tail empty-commits.
// ---------------------------------------------------------------------------
__global__ __launch_bounds__(256, 3) void k2_gemm(
    const float* __restrict__ bias,    // [512]
    float*       __restrict__ out_p)   // [32768,512]
{
    extern __shared__ char sm[];
    const int tid = threadIdx.x;
    const int g   = blockIdx.x;          // 0..2047
    const int bn  = (g & 7) * 64;
    const int bm  = (g >> 3) * 128;
    const int wid = tid >> 5;
    const int lid = tid & 31;
    const int warp_m = wid & 3;
    const int warp_n = wid >> 2;
    const u32 smb = smem_u32(sm);

    const uint4* Asrc = (const uint4*)g_Afrag + (size_t)((bm >> 7) * 8) * 512;
    const uint4* Bsrc = (const uint4*)g_Wfrag
                      + (size_t)((bn >> 7) * 8) * 512 + ((bn >> 6) & 1) * 256;

    auto loadAB = [&](int c, int s) {
        const u32 base = smb + s * STAGE_BYTES;
        const uint4* a = Asrc + c * 512;
        const uint4* b = Bsrc + c * 512;
        cp16(base + tid * 16,         a + tid);
        cp16(base + (tid + 256) * 16, a + tid + 256);
        cp16(base + 8192 + tid * 16,  b + tid);
        CP_COMMIT();
    };

    float acc[2][4][4];
    #pragma unroll
    for (int t = 0; t < 2; t++)
        #pragma unroll
        for (int j = 0; j < 4; j++)
            #pragma unroll
            for (int q = 0; q < 4; q++) acc[t][j][q] = 0.f;

    loadAB(0, 0);
    loadAB(1, 1);
    loadAB(2, 2);

    #pragma unroll 1
    for (int c = 0; c < 8; c++) {
        const int s = c & 3;
        CP_WAIT2();
        __syncthreads();
        if (c + 3 < 8) loadAB(c + 3, (c + 3) & 3);
        else           CP_COMMIT();          // empty group: keeps wait invariant

        const uint4* Asm = (const uint4*)(sm + s * STAGE_BYTES);
        const uint2* Bsm = (const uint2*)(sm + s * STAGE_BYTES + 8192);
        #pragma unroll
        for (int ks = 0; ks < 2; ks++) {
            uint4 afr[2];
            #pragma unroll
            for (int t = 0; t < 2; t++)
                afr[t] = Asm[(warp_m * 2 + t) * 64 + ks * 32 + lid];
            uint2 bfr[4];
            #pragma unroll
            for (int j = 0; j < 4; j++)
                bfr[j] = Bsm[(warp_n * 4 + j) * 64 + ks * 32 + lid];
            #pragma unroll
            for (int t = 0; t < 2; t++)
                #pragma unroll
                for (int j = 0; j < 4; j++)
                    mma_f16(acc[t][j], afr[t], bfr[j]);
        }
    }

    #pragma unroll
    for (int t = 0; t < 2; t++) {
        int m0 = bm + warp_m * 32 + t * 16 + (lid >> 2);
        #pragma unroll
        for (int j = 0; j < 4; j++) {
            int col = bn + warp_n * 32 + j * 8 + (lid & 3) * 2;
            float2 bv = __ldg((const float2*)&bias[col]);
            float2 v0, v1;
            v0.x = acc[t][j][0] + bv.x; v0.y = acc[t][j][1] + bv.y;
            v1.x = acc[t][j][2] + bv.x; v1.y = acc[t][j][3] + bv.y;
            *(float2*)&out_p[(size_t)m0 * NOUT + col] = v0;
            *(float2*)&out_p[(size_t)(m0 + 8) * NOUT + col] = v1;
        }
    }
}

// ---------------------------------------------------------------------------
// inputs: 0 x, 1 categories, 2 charges, 3 edges, 4 node_mask, 5 edge_mask,
//         6 emb_table, 7 W, 8 b_lin
// output: parameters [32768*512] | radial [E] | coord_diff [E*3]
// ---------------------------------------------------------------------------
extern "C" void kernel_launch(void* const* d_in, const int* in_sizes, int n_in,
                              void* d_out, int out_size)
{
    const float* x       = (const float*)d_in[0];
    const int*   cats    = (const int*)  d_in[1];
    const float* charges = (const float*)d_in[2];
    const int*   edges   = (const int*)  d_in[3];
    const float* nmask   = (const float*)d_in[4];
    const float* emb     = (const float*)d_in[6];
    const float* W       = (const float*)d_in[7];
    const float* bias    = (const float*)d_in[8];

    float* out        = (float*)d_out;
    float* out_params = out;
    float* out_radial = out + (size_t)MROWS * NOUT;
    float* out_cd     = out_radial + NEDGE;

    cudaFuncSetAttribute(k2_gemm, cudaFuncAttributeMaxDynamicSharedMemorySize, SM_SIZE);

    k0_setup<<<256, 256>>>(x, W);
    k1_edges_afrag<<<2048, 256>>>(edges, charges, cats, nmask, emb,
                                  out_radial, out_cd);
    k2_gemm<<<2048, 256, SM_SIZE>>>(bias, out_params);
}

// round 14
// speedup vs baseline: 1.0678x; 1.0678x over previous
#include <cuda_runtime.h>
#include <cuda_fp16.h>
#include <cstdint>

#define DIMK   256
#define NOUT   512
#define MROWS  32768
#define NEMB   255
#define NEDGE  4194304

typedef unsigned int u32;

// device scratch
__device__ float4 g_xpad[MROWS];
__device__ u32    g_Wfrag[NOUT * DIMK / 2];            // W  fp16, frag order (256KB)
__device__ u32    g_Afrag[(size_t)MROWS * DIMK / 2];   // h  fp16, frag order (16MB)

// smem: 4 stages x (A 8KB + B 4KB) = 48KB, then 4 mbarriers
#define STAGE_BYTES 12288
#define SM_MBAR     49152
#define SM_SIZE     49216

__device__ __forceinline__ u32 pack_h2(float lo, float hi) {
    __half2 h = __floats2half2_rn(lo, hi);
    return *(u32*)&h;
}
__device__ __forceinline__ u32 smem_u32(const void* p) {
    u32 a;
    asm("{ .reg .u64 t; cvta.to.shared.u64 t, %1; cvt.u32.u64 %0, t; }" : "=r"(a) : "l"(p));
    return a;
}
#define MBARRIER_INIT(mb, n) \
    asm volatile("mbarrier.init.shared.b64 [%0], %1;" :: "r"((u32)(mb)), "r"((u32)(n)) : "memory")
#define MBARRIER_EXPECT_TX(mb, bytes) \
    asm volatile("mbarrier.arrive.expect_tx.shared.b64 _, [%0], %1;" \
                 :: "r"((u32)(mb)), "r"((u32)(bytes)) : "memory")
#define FENCE_ASYNC_SHARED() asm volatile("fence.proxy.async.shared::cta;" ::: "memory")
#define MBARRIER_WAIT_PARITY(mb, ph) do {                                        \
    u32 _m = (u32)(mb), _p = (u32)(ph), _d;                                      \
    asm volatile("{\n\t.reg .pred p;\n\t"                                        \
        "mbarrier.try_wait.parity.acquire.cta.shared::cta.b64 p, [%1], %2;\n\t"  \
        "selp.b32 %0, 1, 0, p;\n\t}" : "=r"(_d) : "r"(_m), "r"(_p) : "memory");  \
    if (!_d) {                                                                   \
        asm volatile("{\n\t.reg .pred P1;\n\tWL_%=:\n\t"                         \
        "mbarrier.try_wait.parity.acquire.cta.shared::cta.b64 P1, [%0], %1, 0x989680;\n\t" \
        "@P1 bra.uni WD_%=;\n\tbra.uni WL_%=;\n\tWD_%=:\n\t}"                    \
        :: "r"(_m), "r"(_p) : "memory");                                         \
    }                                                                            \
} while (0)
__device__ __forceinline__ void bulk_cp(u32 dst, const void* src, u32 bytes, u32 mbar) {
    asm volatile(
        "cp.async.bulk.shared::cluster.global.mbarrier::complete_tx::bytes [%0], [%1], %2, [%3];"
        :: "r"(dst), "l"(src), "r"(bytes), "r"(mbar) : "memory");
}

__device__ __forceinline__ void mma_f16(float* c, uint4 a, uint2 b) {
    asm volatile(
        "mma.sync.aligned.m16n8k16.row.col.f32.f16.f16.f32 "
        "{%0,%1,%2,%3}, {%4,%5,%6,%7}, {%8,%9}, {%0,%1,%2,%3};"
        : "+f"(c[0]), "+f"(c[1]), "+f"(c[2]), "+f"(c[3])
        : "r"(a.x), "r"(a.y), "r"(a.z), "r"(a.w), "r"(b.x), "r"(b.y));
}

// ---------------------------------------------------------------------------
// Prologue (R12 layout): blocks 0..1023 Afrag, 1024..1151 Wfrag, 1152..1279 xpad
// ---------------------------------------------------------------------------
__global__ __launch_bounds__(256) void prologue_kernel(
    const float* __restrict__ x,
    const float* __restrict__ W,
    const float* __restrict__ charges,
    const int*   __restrict__ cats,
    const float* __restrict__ nmask,
    const float* __restrict__ emb)
{
    int bid = blockIdx.x, tid = threadIdx.x;
    if (bid < 1024) {
        #pragma unroll
        for (int i = 0; i < 4; i++) {
            int q      = bid * 1024 + i * 256 + tid;   // uint4 index
            int lane   = q & 31;
            int ks     = (q >> 5) & 1;
            int tile_m = (q >> 6) & 7;
            int kc     = (q >> 9) & 7;
            int mb     = q >> 12;
            int m  = mb * 128 + tile_m * 16 + (lane >> 2);
            int k0 = kc * 32 + ks * 16 + (lane & 3) * 2;

            float msk0 = __ldg(&nmask[m]);
            float msk1 = __ldg(&nmask[m + 8]);
            int   cat0 = __ldg(&cats[m]);
            int   cat1 = __ldg(&cats[m + 8]);
            auto hval = [&](int mm, float msk, int cat, int k) -> float {
                return (k == 0) ? __ldg(&charges[mm]) * msk
                                : __ldg(&emb[cat * NEMB + k - 1]) * msk;
            };
            uint4 v;
            v.x = pack_h2(hval(m,     msk0, cat0, k0),     hval(m,     msk0, cat0, k0 + 1));
            v.y = pack_h2(hval(m + 8, msk1, cat1, k0),     hval(m + 8, msk1, cat1, k0 + 1));
            v.z = pack_h2(hval(m,     msk0, cat0, k0 + 8), hval(m,     msk0, cat0, k0 + 9));
            v.w = pack_h2(hval(m + 8, msk1, cat1, k0 + 8), hval(m + 8, msk1, cat1, k0 + 9));
            ((uint4*)g_Afrag)[q] = v;
        }
    } else if (bid < 1152) {
        int b = bid - 1024;
        #pragma unroll
        for (int i = 0; i < 2; i++) {
            int p      = b * 512 + i * 256 + tid;      // uint2 index
            int lane   = p & 31;
            int ks     = (p >> 5) & 1;
            int tile_n = (p >> 6) & 15;
            int kc     = (p >> 10) & 7;
            int nb     = p >> 13;
            int n  = nb * 128 + tile_n * 8 + (lane >> 2);
            int k0 = kc * 32 + ks * 16 + (lane & 3) * 2;
            uint2 v;
            v.x = pack_h2(W[k0 * NOUT + n],       W[(k0 + 1) * NOUT + n]);
            v.y = pack_h2(W[(k0 + 8) * NOUT + n], W[(k0 + 9) * NOUT + n]);
            ((uint2*)g_Wfrag)[p] = v;
        }
    } else {
        int i = (bid - 1152) * 256 + tid;
        if (i < MROWS)
            g_xpad[i] = make_float4(x[3 * i], x[3 * i + 1], x[3 * i + 2], 0.f);
    }
}

// ---------------------------------------------------------------------------
// Fused kernel, grid 4096: even bidx -> GEMM (2048 tiles of 128x64),
// odd bidx -> edges (sync-free, 8 edges/thread).
// GEMM loads via cp.async.bulk (one 8KB + one 4KB per chunk, tid0-issued),
// 4-stage tx-mbarrier pipeline, distance 3, one __syncthreads per chunk.
// ---------------------------------------------------------------------------
__global__ __launch_bounds__(256, 3) void fused_kernel(
    const float* __restrict__ bias,    // [512]
    const int*   __restrict__ edges,   // [2,E]
    float*       __restrict__ out_p,   // [32768,512]
    float*       __restrict__ radial,  // [E]
    float*       __restrict__ cd)      // [E,3]
{
    extern __shared__ char sm[];
    const int tid  = threadIdx.x;
    const int bidx = blockIdx.x;

    if ((bidx & 1) == 0) {
        // =========================== GEMM ===========================
        const int g  = bidx >> 1;            // 0..2047
        const int bn = (g & 7) * 64;
        const int bm = (g >> 3) * 128;
        const int wid = tid >> 5;
        const int lid = tid & 31;
        const int warp_m = wid & 3;
        const int warp_n = wid >> 2;
        const u32 smb = smem_u32(sm);

        const uint4* Asrc = (const uint4*)g_Afrag + (size_t)((bm >> 7) * 8) * 512;
        const uint4* Bsrc = (const uint4*)g_Wfrag
                          + (size_t)((bn >> 7) * 8) * 512 + ((bn >> 6) & 1) * 256;

        if (tid == 0) {
            #pragma unroll
            for (int s = 0; s < 4; s++) MBARRIER_INIT(smb + SM_MBAR + s * 8, 1);
        }
        __syncthreads();

        auto issue = [&](int c) {
            const int s = c & 3;
            const u32 base = smb + s * STAGE_BYTES;
            const u32 mb   = smb + SM_MBAR + s * 8;
            MBARRIER_EXPECT_TX(mb, 12288);
            bulk_cp(base,        Asrc + c * 512, 8192, mb);
            bulk_cp(base + 8192, Bsrc + c * 512, 4096, mb);
        };

        if (tid == 0) {
            FENCE_ASYNC_SHARED();
            issue(0); issue(1); issue(2);
        }

        float acc[2][4][4];
        #pragma unroll
        for (int t = 0; t < 2; t++)
            #pragma unroll
            for (int j = 0; j < 4; j++)
                #pragma unroll
                for (int q = 0; q < 4; q++) acc[t][j][q] = 0.f;

        #pragma unroll 1
        for (int c = 0; c < 8; c++) {
            const int s = c & 3;
            MBARRIER_WAIT_PARITY(smb + SM_MBAR + s * 8, (c >> 2) & 1);

            const uint4* Asm = (const uint4*)(sm + s * STAGE_BYTES);
            const uint2* Bsm = (const uint2*)(sm + s * STAGE_BYTES + 8192);
            #pragma unroll
            for (int ks = 0; ks < 2; ks++) {
                uint4 afr[2];
                #pragma unroll
                for (int t = 0; t < 2; t++)
                    afr[t] = Asm[(warp_m * 2 + t) * 64 + ks * 32 + lid];
                uint2 bfr[4];
                #pragma unroll
                for (int j = 0; j < 4; j++)
                    bfr[j] = Bsm[(warp_n * 4 + j) * 64 + ks * 32 + lid];
                #pragma unroll
                for (int t = 0; t < 2; t++)
                    #pragma unroll
                    for (int j = 0; j < 4; j++)
                        mma_f16(acc[t][j], afr[t], bfr[j]);
            }
            __syncthreads();                 // all consumed stage (c-1)&3 by now
            if (tid == 0 && c + 3 < 8) issue(c + 3);
        }

        // epilogue: bias + float2 stores
        #pragma unroll
        for (int t = 0; t < 2; t++) {
            int m0 = bm + warp_m * 32 + t * 16 + (lid >> 2);
            #pragma unroll
            for (int j = 0; j < 4; j++) {
                int col = bn + warp_n * 32 + j * 8 + (lid & 3) * 2;
                float2 bv = __ldg((const float2*)&bias[col]);
                float2 v0, v1;
                v0.x = acc[t][j][0] + bv.x; v0.y = acc[t][j][1] + bv.y;
                v1.x = acc[t][j][2] + bv.x; v1.y = acc[t][j][3] + bv.y;
                *(float2*)&out_p[(size_t)m0 * NOUT + col] = v0;
                *(float2*)&out_p[(size_t)(m0 + 8) * NOUT + col] = v1;
            }
        }
    } else {
        // ================= edges: sync-free, 8 consecutive per thread =========
        const int eid  = bidx >> 1;               // 0..2047
        const int b4   = eid * 512 + tid;         // first int4 index
        const int4* rowp = (const int4*)edges;
        const int4* colp = (const int4*)(edges + NEDGE);

        #pragma unroll
        for (int it = 0; it < 2; it++) {
            int q4 = b4 + it * 256;               // int4 / float4 index (4 edges)
            int4 r = __ldg(&rowp[q4]);
            int4 c = __ldg(&colp[q4]);
            float4 p0 = __ldg(&g_xpad[r.x]);
            float4 p1 = __ldg(&g_xpad[r.y]);
            float4 p2 = __ldg(&g_xpad[r.z]);
            float4 p3 = __ldg(&g_xpad[r.w]);
            float4 q0 = __ldg(&g_xpad[c.x]);
            float4 q1 = __ldg(&g_xpad[c.y]);
            float4 q2 = __ldg(&g_xpad[c.z]);
            float4 q3 = __ldg(&g_xpad[c.w]);

            float d0x = p0.x - q0.x, d0y = p0.y - q0.y, d0z = p0.z - q0.z;
            float d1x = p1.x - q1.x, d1y = p1.y - q1.y, d1z = p1.z - q1.z;
            float d2x = p2.x - q2.x, d2y = p2.y - q2.y, d2z = p2.z - q2.z;
            float d3x = p3.x - q3.x, d3y = p3.y - q3.y, d3z = p3.z - q3.z;

            float4 rad;
            rad.x = d0x*d0x + d0y*d0y + d0z*d0z;
            rad.y = d1x*d1x + d1y*d1y + d1z*d1z;
            rad.z = d2x*d2x + d2y*d2y + d2z*d2z;
            rad.w = d3x*d3x + d3y*d3y + d3z*d3z;

            float i0 = 1.0f / (sqrtf(rad.x + 1e-8f) + 1.0f);
            float i1 = 1.0f / (sqrtf(rad.y + 1e-8f) + 1.0f);
            float i2 = 1.0f / (sqrtf(rad.z + 1e-8f) + 1.0f);
            float i3 = 1.0f / (sqrtf(rad.w + 1e-8f) + 1.0f);

            ((float4*)radial)[q4] = rad;

            float4* dst = (float4*)cd + (size_t)q4 * 3;
            dst[0] = make_float4(d0x * i0, d0y * i0, d0z * i0, d1x * i1);
            dst[1] = make_float4(d1y * i1, d1z * i1, d2x * i2, d2y * i2);
            dst[2] = make_float4(d2z * i2, d3x * i3, d3y * i3, d3z * i3);
        }
    }
}

// ---------------------------------------------------------------------------
// inputs: 0 x, 1 categories, 2 charges, 3 edges, 4 node_mask, 5 edge_mask,
//         6 emb_table, 7 W, 8 b_lin
// output: parameters [32768*512] | radial [E] | coord_diff [E*3]
// ---------------------------------------------------------------------------
extern "C" void kernel_launch(void* const* d_in, const int* in_sizes, int n_in,
                              void* d_out, int out_size)
{
    const float* x       = (const float*)d_in[0];
    const int*   cats    = (const int*)  d_in[1];
    const float* charges = (const float*)d_in[2];
    const int*   edges   = (const int*)  d_in[3];
    const float* nmask   = (const float*)d_in[4];
    const float* emb     = (const float*)d_in[6];
    const float* W       = (const float*)d_in[7];
    const float* bias    = (const float*)d_in[8];

    float* out        = (float*)d_out;
    float* out_params = out;
    float* out_radial = out + (size_t)MROWS * NOUT;
    float* out_cd     = out_radial + NEDGE;

    cudaFuncSetAttribute(fused_kernel, cudaFuncAttributeMaxDynamicSharedMemorySize, SM_SIZE);

    prologue_kernel<<<1280, 256>>>(x, W, charges, cats, nmask, emb);
    fused_kernel<<<4096, 256, SM_SIZE>>>(bias, edges, out_params, out_radial, out_cd);
}